// round 15
// baseline (speedup 1.0000x reference)
#include <cuda_runtime.h>
#include <cuda_bf16.h>
#include <cuda_fp16.h>
#include <cstdint>
#include <cstddef>

#define NENT  50000
#define NREL  16
#define NBAS  8
#define DIM   128
#define NEDGE 800000
#define KAGG  (NBAS * DIM)     // 1024
#define KTOT  (KAGG + DIM)     // 1152 = aggB(1024) ‖ h(128)
#define KC    32               // k per GEMM chunk
#define NCH   (KTOT / KC)      // 36
#define GM    128              // rows per CTA tile
#define ASTR  80               // smem row stride bytes (64B data + 16B shift -> conflict-free)
#define PLANE (128 * ASTR)     // 10240 B per smem plane
#define STAGE (4 * PLANE)      // 40960 B per pipeline stage

typedef unsigned long long ull;

// ---------------- scratch (static device globals; no allocation) ----------------
__device__ __align__(128) __half g_agg[(size_t)NENT * NREL * DIM];           // 204.8 MB (fp16)
__device__ __align__(128) float  g_h1 [(size_t)NENT * DIM];                  // 25.6 MB
// A = [aggB | h] as bf16 hi/lo planes, [NENT][KTOT]
__device__ __align__(128) __nv_bfloat16 g_Ah[(size_t)NENT * KTOT];           // 115.2 MB
__device__ __align__(128) __nv_bfloat16 g_Al[(size_t)NENT * KTOT];           // 115.2 MB
// W = [basis | loop_w] as bf16 hi/lo planes, [n=128][k=KTOT]
__device__ __align__(128) __nv_bfloat16 g_Wh[(size_t)128 * KTOT];
__device__ __align__(128) __nv_bfloat16 g_Wl[(size_t)128 * KTOT];

// ---------------- helpers ----------------
__device__ __forceinline__ uint32_t smem_u32(const void* p) {
    uint32_t a;
    asm("{ .reg .u64 t; cvta.to.shared.u64 t, %1; cvt.u32.u64 %0, t; }" : "=r"(a) : "l"(p));
    return a;
}
__device__ __forceinline__ uint32_t bf2_bits(__nv_bfloat16 a, __nv_bfloat16 b) {
    __nv_bfloat162 t = __halves2bfloat162(a, b);   // a -> low 16 bits
    return *reinterpret_cast<uint32_t*>(&t);
}
__device__ __forceinline__ uint2 split4(float4 v, uint2& lo) {
    __nv_bfloat16 h0 = __float2bfloat16(v.x);
    __nv_bfloat16 h1 = __float2bfloat16(v.y);
    __nv_bfloat16 h2 = __float2bfloat16(v.z);
    __nv_bfloat16 h3 = __float2bfloat16(v.w);
    lo = make_uint2(bf2_bits(__float2bfloat16(v.x - __bfloat162float(h0)),
                             __float2bfloat16(v.y - __bfloat162float(h1))),
                    bf2_bits(__float2bfloat16(v.z - __bfloat162float(h2)),
                             __float2bfloat16(v.w - __bfloat162float(h3))));
    return make_uint2(bf2_bits(h0, h1), bf2_bits(h2, h3));
}
__device__ __forceinline__ void ldsm4(uint32_t* r, uint32_t addr) {
    asm volatile("ldmatrix.sync.aligned.m8n8.x4.shared.b16 {%0,%1,%2,%3}, [%4];"
                 : "=r"(r[0]), "=r"(r[1]), "=r"(r[2]), "=r"(r[3]) : "r"(addr));
}
__device__ __forceinline__ void mma16816(float* d, const uint32_t* a, const uint32_t* b) {
    asm volatile(
        "mma.sync.aligned.m16n8k16.row.col.f32.bf16.bf16.f32 "
        "{%0,%1,%2,%3}, {%4,%5,%6,%7}, {%8,%9}, {%0,%1,%2,%3};"
        : "+f"(d[0]), "+f"(d[1]), "+f"(d[2]), "+f"(d[3])
        : "r"(a[0]), "r"(a[1]), "r"(a[2]), "r"(a[3]), "r"(b[0]), "r"(b[1]));
}
__device__ __forceinline__ void cp16(uint32_t saddr, const void* gaddr) {
    asm volatile("cp.async.cg.shared.global [%0], [%1], 16;"
                 :: "r"(saddr), "l"(gaddr) : "memory");
}
#define CP_COMMIT()  asm volatile("cp.async.commit_group;" ::: "memory")
#define CP_WAIT(n)   asm volatile("cp.async.wait_group %0;" :: "n"(n) : "memory")

// ---------------- kernel: edge scatter  agg[dst,rel] += h[src]  (fp16 atomics) ----------------
__global__ void k_scatter(const float* __restrict__ h,
                          const int* __restrict__ src,
                          const int* __restrict__ dst,
                          const int* __restrict__ rel) {
    int lane  = threadIdx.x & 31;
    int warp  = (blockIdx.x * blockDim.x + threadIdx.x) >> 5;
    int nwarp = (gridDim.x * blockDim.x) >> 5;
    for (int e = warp; e < NEDGE; e += nwarp) {
        int s = __ldg(src + e);
        int d = __ldg(dst + e);
        int r = __ldg(rel + e);
        float4 v = __ldg(reinterpret_cast<const float4*>(h + (size_t)s * DIM) + lane);
        __half2 a = __floats2half2_rn(v.x, v.y);   // x -> low half
        __half2 b = __floats2half2_rn(v.z, v.w);
        uint32_t ua = *reinterpret_cast<uint32_t*>(&a);
        uint32_t ub = *reinterpret_cast<uint32_t*>(&b);
        __half* p = g_agg + ((size_t)d * NREL + r) * DIM + lane * 4;
        asm volatile("red.global.add.noftz.f16x2 [%0], %1;" :: "l"(p),     "r"(ua) : "memory");
        asm volatile("red.global.add.noftz.f16x2 [%0], %1;" :: "l"(p + 2), "r"(ub) : "memory");
    }
}

// ---------------- kernel: contraction (fp16 in) + bf16 hi/lo split out ----------------
// g_A{h,l}[n][b*128 + i] = split( sum_r wcomp[r,b] * agg[n,r,i] )
__global__ void k_contract(const float* __restrict__ wcomp) {
    __shared__ float wc[NREL * NBAS];
    int t = threadIdx.x;
    if (t < NREL * NBAS) wc[t] = wcomp[t];
    __syncthreads();

    int idx = blockIdx.x * blockDim.x + t;
    if (idx >= NENT * 32) return;
    int n  = idx >> 5;
    int iq = idx & 31;

    const uint2* ag = reinterpret_cast<const uint2*>(g_agg) + (size_t)n * (NREL * 32);
    float4 acc[NBAS];
#pragma unroll
    for (int b = 0; b < NBAS; b++) acc[b] = make_float4(0.f, 0.f, 0.f, 0.f);
#pragma unroll
    for (int r = 0; r < NREL; r++) {
        uint2 u = ag[r * 32 + iq];
        __half2 p0 = *reinterpret_cast<__half2*>(&u.x);
        __half2 p1 = *reinterpret_cast<__half2*>(&u.y);
        float4 v = make_float4(__low2float(p0), __high2float(p0),
                               __low2float(p1), __high2float(p1));
#pragma unroll
        for (int b = 0; b < NBAS; b++) {
            float w = wc[r * NBAS + b];
            acc[b].x = fmaf(w, v.x, acc[b].x);
            acc[b].y = fmaf(w, v.y, acc[b].y);
            acc[b].z = fmaf(w, v.z, acc[b].z);
            acc[b].w = fmaf(w, v.w, acc[b].w);
        }
    }
#pragma unroll
    for (int b = 0; b < NBAS; b++) {
        uint2 lo;
        uint2 hi = split4(acc[b], lo);
        size_t off = (size_t)n * KTOT + b * DIM + iq * 4;
        *reinterpret_cast<uint2*>(g_Ah + off) = hi;
        *reinterpret_cast<uint2*>(g_Al + off) = lo;
    }
}

// ---------------- kernel: self-loop input -> A plane cols 1024..1151 ----------------
__global__ void k_convert_h(const float* __restrict__ h) {
    int gid = blockIdx.x * blockDim.x + threadIdx.x;
    if (gid >= NENT * 32) return;
    int n  = gid >> 5;
    int jq = (gid & 31) * 4;
    float4 v = __ldg(reinterpret_cast<const float4*>(h + (size_t)n * DIM + jq));
    uint2 lo;
    uint2 hi = split4(v, lo);
    size_t off = (size_t)n * KTOT + KAGG + jq;
    *reinterpret_cast<uint2*>(g_Ah + off) = hi;
    *reinterpret_cast<uint2*>(g_Al + off) = lo;
}

// ---------------- kernel: W -> bf16 hi/lo planes, [n][k] ----------------
__global__ void k_convert_w(const float* __restrict__ basis,
                            const float* __restrict__ loopw) {
    int gid = blockIdx.x * blockDim.x + threadIdx.x;
    if (gid >= 128 * KTOT) return;
    int n = gid / KTOT;
    int k = gid % KTOT;
    float v = (k < KAGG) ? __ldg(basis + (size_t)k * DIM + n)
                         : __ldg(loopw + (size_t)(k - KAGG) * DIM + n);
    __nv_bfloat16 hi = __float2bfloat16(v);
    g_Wh[gid] = hi;
    g_Wl[gid] = __float2bfloat16(v - __bfloat162float(hi));
}

// ---------------- kernel: tensor-core GEMM (cp.async double-buffered) ----------------
// out[m,:] = relu( A[m,:1152] @ W + bias ),  Ah·Wh + Al·Wh + Ah·Wl, fp32 accum.
// CTA: 256 thr (8 warps, 4M x 2N), tile 128x128; warp tile 32x64; K chunk 32;
// 2-stage cp.async pipeline, smem stride 80B (conflict-free ldmatrix).
__global__ __launch_bounds__(256, 2)
void k_gemm_tc(const float* __restrict__ bias, float* __restrict__ out) {
    extern __shared__ char sm[];
    const uint32_t usm = smem_u32(sm);

    const int t    = threadIdx.x;
    const int l    = t & 31;
    const int w    = t >> 5;
    const int mw   = w >> 1;          // 0..3
    const int nw   = w & 1;           // 0..1
    const int grp  = l >> 2;
    const int tig  = l & 3;
    const int sub  = l >> 3;
    const int lr   = l & 7;
    const int row0 = blockIdx.x * GM;

    const uint32_t aOff = (uint32_t)((mw * 32 + lr + (sub & 1) * 8) * ASTR + ((sub >> 1) * 16));
    const uint32_t wOff = (uint32_t)((nw * 64 + lr + (sub >> 1) * 8) * ASTR + ((sub & 1) * 16));

    // staging geometry: 512 16B-units per plane; 2 per thread per plane
    const int sn0 = t >> 2;           // row for unit idx=t        (0..63)
    const int su0 = t & 3;
    const int sn1 = (t + 256) >> 2;   // row for unit idx=t+256    (64..127)
    const int su1 = su0;

    float d[2][8][4];
#pragma unroll
    for (int mt = 0; mt < 2; mt++)
#pragma unroll
        for (int nt = 0; nt < 8; nt++)
#pragma unroll
            for (int e = 0; e < 4; e++) d[mt][nt][e] = 0.f;

    // ---- stage chunk c into buffer s ----
    auto stage = [&](int c, int s) {
        const int k0 = c * KC;
        const uint32_t ub = usm + s * STAGE;
        int gr0 = row0 + sn0; if (gr0 > NENT - 1) gr0 = NENT - 1;
        int gr1 = row0 + sn1; if (gr1 > NENT - 1) gr1 = NENT - 1;
        {
            size_t ga = (size_t)gr0 * KTOT + k0 + su0 * 8;
            size_t gw = (size_t)sn0 * KTOT + k0 + su0 * 8;
            uint32_t so = sn0 * ASTR + su0 * 16;
            cp16(ub + so,             g_Ah + ga);
            cp16(ub + PLANE + so,     g_Al + ga);
            cp16(ub + 2 * PLANE + so, g_Wh + gw);
            cp16(ub + 3 * PLANE + so, g_Wl + gw);
        }
        {
            size_t ga = (size_t)gr1 * KTOT + k0 + su1 * 8;
            size_t gw = (size_t)sn1 * KTOT + k0 + su1 * 8;
            uint32_t so = sn1 * ASTR + su1 * 16;
            cp16(ub + so,             g_Ah + ga);
            cp16(ub + PLANE + so,     g_Al + ga);
            cp16(ub + 2 * PLANE + so, g_Wh + gw);
            cp16(ub + 3 * PLANE + so, g_Wl + gw);
        }
    };

    stage(0, 0);
    CP_COMMIT();

    for (int c = 0; c < NCH; c++) {
        if (c + 1 < NCH) {
            stage(c + 1, (c + 1) & 1);
            CP_COMMIT();
            CP_WAIT(1);
        } else {
            CP_WAIT(0);
        }
        __syncthreads();

        const uint32_t uAh = usm + (c & 1) * STAGE;
        const uint32_t uAl = uAh + PLANE;
        const uint32_t uWh = uAh + 2 * PLANE;
        const uint32_t uWl = uAh + 3 * PLANE;

#pragma unroll
        for (int ks = 0; ks < KC / 16; ks++) {
            const uint32_t kb = (uint32_t)(ks * 32);
            uint32_t A[2][4], A2[2][4], W[4][4];
            ldsm4(A[0], uAh + aOff + kb);
            ldsm4(A[1], uAh + aOff + kb + 16 * ASTR);
#pragma unroll
            for (int j = 0; j < 4; j++) ldsm4(W[j], uWh + wOff + kb + j * 16 * ASTR);
            // Ah * Wh
#pragma unroll
            for (int mt = 0; mt < 2; mt++)
#pragma unroll
                for (int j = 0; j < 4; j++) {
                    mma16816(d[mt][2 * j],     A[mt], &W[j][0]);
                    mma16816(d[mt][2 * j + 1], A[mt], &W[j][2]);
                }
            // Al * Wh
            ldsm4(A2[0], uAl + aOff + kb);
            ldsm4(A2[1], uAl + aOff + kb + 16 * ASTR);
#pragma unroll
            for (int mt = 0; mt < 2; mt++)
#pragma unroll
                for (int j = 0; j < 4; j++) {
                    mma16816(d[mt][2 * j],     A2[mt], &W[j][0]);
                    mma16816(d[mt][2 * j + 1], A2[mt], &W[j][2]);
                }
            // Ah * Wl
#pragma unroll
            for (int j = 0; j < 4; j++) ldsm4(W[j], uWl + wOff + kb + j * 16 * ASTR);
#pragma unroll
            for (int mt = 0; mt < 2; mt++)
#pragma unroll
                for (int j = 0; j < 4; j++) {
                    mma16816(d[mt][2 * j],     A[mt], &W[j][0]);
                    mma16816(d[mt][2 * j + 1], A[mt], &W[j][2]);
                }
        }
        __syncthreads();
    }

    // ---- epilogue: bias + ReLU, fp32 stores ----
    const int rbase = row0 + mw * 32 + grp;
#pragma unroll
    for (int mt = 0; mt < 2; mt++) {
        int rA = rbase + mt * 16;
        int rB = rA + 8;
#pragma unroll
        for (int nt = 0; nt < 8; nt++) {
            int cc = nw * 64 + nt * 8 + tig * 2;
            float2 bb = __ldg(reinterpret_cast<const float2*>(bias + cc));
            if (rA < NENT) {
                float2 o;
                o.x = fmaxf(d[mt][nt][0] + bb.x, 0.f);
                o.y = fmaxf(d[mt][nt][1] + bb.y, 0.f);
                *reinterpret_cast<float2*>(out + (size_t)rA * DIM + cc) = o;
            }
            if (rB < NENT) {
                float2 o;
                o.x = fmaxf(d[mt][nt][2] + bb.x, 0.f);
                o.y = fmaxf(d[mt][nt][3] + bb.y, 0.f);
                *reinterpret_cast<float2*>(out + (size_t)rB * DIM + cc) = o;
            }
        }
    }
}

// ---------------- launcher ----------------
extern "C" void kernel_launch(void* const* d_in, const int* in_sizes, int n_in,
                              void* d_out, int out_size) {
    const float* emb    = (const float*)d_in[0];
    const float* basis1 = (const float*)d_in[1];
    const float* wcomp1 = (const float*)d_in[2];
    const float* loopw1 = (const float*)d_in[3];
    const float* bias1  = (const float*)d_in[4];
    const float* basis2 = (const float*)d_in[5];
    const float* wcomp2 = (const float*)d_in[6];
    const float* loopw2 = (const float*)d_in[7];
    const float* bias2  = (const float*)d_in[8];
    const int*   src    = (const int*)d_in[9];
    const int*   dst    = (const int*)d_in[10];
    const int*   rel    = (const int*)d_in[11];
    float*       out    = (float*)d_out;

    void* h1p_ = nullptr;
    cudaGetSymbolAddress(&h1p_, g_h1);      // address query only; no allocation
    float* h1p = (float*)h1p_;
    void* aggp_ = nullptr;
    cudaGetSymbolAddress(&aggp_, g_agg);
    const size_t agg_bytes = (size_t)NENT * NREL * DIM * sizeof(__half);   // 204.8 MB

    const int CB = (NENT * 32 + 255) / 256;
    const int GB = (NENT + GM - 1) / GM;             // 391
    const int WB = (128 * KTOT + 255) / 256;         // 576
    const int SMEM_GEMM = 2 * STAGE;                 // 81920

    cudaFuncSetAttribute(k_gemm_tc, cudaFuncAttributeMaxDynamicSharedMemorySize, SMEM_GEMM);

    // ---- layer 1 ----
    cudaMemsetAsync(aggp_, 0, agg_bytes);
    k_scatter<<<2048, 256>>>(emb, src, dst, rel);
    k_contract<<<CB, 256>>>(wcomp1);
    k_convert_h<<<CB, 256>>>(emb);
    k_convert_w<<<WB, 256>>>(basis1, loopw1);
    k_gemm_tc<<<GB, 256, SMEM_GEMM>>>(bias1, h1p);

    // ---- layer 2 ----
    cudaMemsetAsync(aggp_, 0, agg_bytes);
    k_scatter<<<2048, 256>>>(h1p, src, dst, rel);
    k_contract<<<CB, 256>>>(wcomp2);
    k_convert_h<<<CB, 256>>>(h1p);
    k_convert_w<<<WB, 256>>>(basis2, loopw2);
    k_gemm_tc<<<GB, 256, SMEM_GEMM>>>(bias2, out);
}